// round 4
// baseline (speedup 1.0000x reference)
#include <cuda_runtime.h>

// NonLocalAttention: B=4, C=256, H=W=64 -> N=4096, C8=32, C2=128
//   proj_tc_kernel : theta/phi/g projections, tf32 mma with split-x (2xtf32)
//   flash_tc_kernel: tf32 mma flash attention, theta in smem, 4 CTA/SM
//   out_tc_kernel  : w_o @ att + b_o + x, tf32 mma with split-att

#define B_ 4
#define C_ 256
#define N_ 4096
#define C8_ 32
#define C2_ 128

__device__ float d_theta[B_ * C8_ * N_];
__device__ float d_phi[B_ * C8_ * N_];
__device__ float d_g[(size_t)B_ * N_ * C2_];
__device__ float d_att[(size_t)B_ * N_ * C2_];

// ---- intrinsics ----
__device__ __forceinline__ unsigned cvt_tf32(float x) {
    unsigned r;
    asm("cvt.rna.tf32.f32 %0, %1;" : "=r"(r) : "f"(x));
    return r;
}
__device__ __forceinline__ float cvt_tf32f(float x) {
    return __uint_as_float(cvt_tf32(x));
}
__device__ __forceinline__ float ex2f(float x) {
    float r;
    asm("ex2.approx.f32 %0, %1;" : "=f"(r) : "f"(x));
    return r;
}
__device__ __forceinline__ void mma_tf32(
    float& c0, float& c1, float& c2, float& c3,
    unsigned a0, unsigned a1, unsigned a2, unsigned a3,
    unsigned b0, unsigned b1) {
    asm("mma.sync.aligned.m16n8k8.row.col.f32.tf32.tf32.f32 "
        "{%0,%1,%2,%3}, {%4,%5,%6,%7}, {%8,%9}, {%0,%1,%2,%3};"
        : "+f"(c0), "+f"(c1), "+f"(c2), "+f"(c3)
        : "r"(a0), "r"(a1), "r"(a2), "r"(a3), "r"(b0), "r"(b1));
}

// ============================================================================
// Kernel 1: projections via tf32 mma, split-x. (unchanged from R3)
// ============================================================================
__global__ void __launch_bounds__(256) proj_tc_kernel(
    const float* __restrict__ x,
    const float* __restrict__ wt, const float* __restrict__ bt,
    const float* __restrict__ wp, const float* __restrict__ bp,
    const float* __restrict__ wg, const float* __restrict__ bg) {
    extern __shared__ float sm[];
    float* ws = sm;                 // [32][36]   tf32 weights (k-phase)
    float* xh = sm + 32 * 36;       // [32][264]  x hi
    float* xl = xh + 32 * 264;      // [32][264]  x lo

    const int b  = blockIdx.y;
    const int Mbase = (blockIdx.x >> 4) * 32;
    const int N0    = (blockIdx.x & 15) * 256;
    const int tid  = threadIdx.x;
    const int wid  = tid >> 5, lane = tid & 31;
    const int m0   = (wid >> 2) * 16;
    const int n0w  = (wid & 3) * 64;
    const int qr = lane >> 2, qc = lane & 3;

    float acc[8][4];
#pragma unroll
    for (int nt = 0; nt < 8; nt++)
#pragma unroll
        for (int j = 0; j < 4; j++) acc[nt][j] = 0.f;

    for (int kp = 0; kp < 8; kp++) {
        const int k0 = kp * 32;
        __syncthreads();
#pragma unroll
        for (int i = 0; i < 4; i++) {
            int idx = i * 256 + tid;
            int r = idx >> 5, kk = idx & 31;
            int o = Mbase + r;
            const float* src = (o < 32) ? wt + o * C_
                             : (o < 64) ? wp + (o - 32) * C_
                                        : wg + (o - 64) * C_;
            ws[r * 36 + kk] = cvt_tf32f(src[k0 + kk]);
        }
#pragma unroll
        for (int i = 0; i < 8; i++) {
            int idx = i * 256 + tid;
            int cc = idx >> 6, nn4 = idx & 63;
            float4 v = *(const float4*)(
                x + ((size_t)(b * C_ + k0 + cc)) * N_ + N0 + nn4 * 4);
            float4 h, l;
            h.x = cvt_tf32f(v.x); l.x = v.x - h.x;
            h.y = cvt_tf32f(v.y); l.y = v.y - h.y;
            h.z = cvt_tf32f(v.z); l.z = v.z - h.z;
            h.w = cvt_tf32f(v.w); l.w = v.w - h.w;
            *(float4*)(xh + cc * 264 + nn4 * 4) = h;
            *(float4*)(xl + cc * 264 + nn4 * 4) = l;
        }
        __syncthreads();

#pragma unroll
        for (int ks = 0; ks < 4; ks++) {
            const float* wrow = ws + (m0 + qr) * 36 + ks * 8 + qc;
            unsigned a0 = __float_as_uint(wrow[0]);
            unsigned a1 = __float_as_uint(wrow[8 * 36]);
            unsigned a2 = __float_as_uint(wrow[4]);
            unsigned a3 = __float_as_uint(wrow[8 * 36 + 4]);
            const float* bh = xh + (ks * 8 + qc) * 264 + n0w + qr;
            const float* bl = xl + (ks * 8 + qc) * 264 + n0w + qr;
#pragma unroll
            for (int nt = 0; nt < 8; nt++) {
                unsigned b0 = __float_as_uint(bh[nt * 8]);
                unsigned b1 = __float_as_uint(bh[4 * 264 + nt * 8]);
                mma_tf32(acc[nt][0], acc[nt][1], acc[nt][2], acc[nt][3],
                         a0, a1, a2, a3, b0, b1);
                unsigned l0 = __float_as_uint(bl[nt * 8]);
                unsigned l1 = __float_as_uint(bl[4 * 264 + nt * 8]);
                mma_tf32(acc[nt][0], acc[nt][1], acc[nt][2], acc[nt][3],
                         a0, a1, a2, a3, l0, l1);
            }
        }
    }

#pragma unroll
    for (int rr = 0; rr < 2; rr++) {
        int o = Mbase + m0 + qr + rr * 8;
        if (o < 32) {
            float bias = bt[o];
            float* dst = d_theta + ((size_t)b * C8_ + o) * N_ + N0 + n0w + qc * 2;
#pragma unroll
            for (int nt = 0; nt < 8; nt++)
                *(float2*)(dst + nt * 8) = make_float2(
                    acc[nt][rr * 2] + bias, acc[nt][rr * 2 + 1] + bias);
        } else if (o < 64) {
            float bias = bp[o - 32];
            float* dst = d_phi + ((size_t)b * C8_ + (o - 32)) * N_ + N0 + n0w + qc * 2;
#pragma unroll
            for (int nt = 0; nt < 8; nt++)
                *(float2*)(dst + nt * 8) = make_float2(
                    acc[nt][rr * 2] + bias, acc[nt][rr * 2 + 1] + bias);
        } else {
            int c2 = o - 64;
            float bias = bg[c2];
#pragma unroll
            for (int nt = 0; nt < 8; nt++) {
                int n = N0 + n0w + qc * 2 + nt * 8;
                d_g[((size_t)b * N_ + n) * C2_ + c2]     = acc[nt][rr * 2] + bias;
                d_g[((size_t)b * N_ + n + 1) * C2_ + c2] = acc[nt][rr * 2 + 1] + bias;
            }
        }
    }
}

// ============================================================================
// Kernel 2: tf32 flash attention, theta staged in smem, 4 CTA/SM target.
// ============================================================================
__global__ void __launch_bounds__(128, 4) flash_tc_kernel() {
    extern __shared__ float sm[];
    float* th_s  = sm;               // [64][36]  theta[q][c] * log2e (tf32)
    float* phi_s = sm + 64 * 36;     // [64][36]  phi[k][c]   (tf32)
    float* g_s   = sm + 2 * 64 * 36; // [64][136] g[k][c2]    (tf32)

    const int b   = blockIdx.y;
    const int q0  = blockIdx.x * 64;
    const int tid = threadIdx.x;
    const int w    = tid >> 5;
    const int lane = tid & 31;
    const int qr = lane >> 2;
    const int qc = lane & 3;
    const int row0 = q0 + w * 16 + qr;

    const float LOG2E = 1.4426950408889634f;
    // stage theta once: th_s[q][c] = tf32(theta[b][c][q0+q] * log2e)
    for (int idx = tid; idx < 2048; idx += 128) {
        int c = idx >> 6, q = idx & 63;
        th_s[q * 36 + c] =
            cvt_tf32f(d_theta[((size_t)b * C8_ + c) * N_ + q0 + q] * LOG2E);
    }

    float O[16][4];
#pragma unroll
    for (int nt = 0; nt < 16; nt++)
#pragma unroll
        for (int j = 0; j < 4; j++) O[nt][j] = 0.f;
    float l0 = 0.f, l1 = 0.f;

    const int srcA = (lane & ~3) | ((lane & 3) >> 1);
    const int srcB = srcA + 2;
    const bool odd = lane & 1;

    for (int kt = 0; kt < N_; kt += 64) {
        __syncthreads();
#pragma unroll
        for (int it = 0; it < 16; it++) {
            int idx = it * 128 + tid;
            int c = idx >> 6, k = idx & 63;
            phi_s[k * 36 + c] =
                cvt_tf32f(d_phi[((size_t)b * C8_ + c) * N_ + kt + k]);
        }
        {
            const float4* gg = (const float4*)(d_g + ((size_t)b * N_ + kt) * C2_);
#pragma unroll
            for (int it = 0; it < 16; it++) {
                int idx = it * 128 + tid;
                int k = idx >> 5, c4 = idx & 31;
                float4 v = gg[idx];
                v.x = cvt_tf32f(v.x); v.y = cvt_tf32f(v.y);
                v.z = cvt_tf32f(v.z); v.w = cvt_tf32f(v.w);
                *(float4*)(g_s + k * 136 + c4 * 4) = v;
            }
        }
        __syncthreads();

        // GEMM1: S = theta x phi^T  (A-frags from smem per kc)
        float s[8][4];
#pragma unroll
        for (int nt = 0; nt < 8; nt++)
#pragma unroll
            for (int j = 0; j < 4; j++) s[nt][j] = 0.f;

#pragma unroll
        for (int kc = 0; kc < 4; kc++) {
            const float* ta = th_s + (w * 16 + qr) * 36 + kc * 8 + qc;
            unsigned a0 = __float_as_uint(ta[0]);
            unsigned a1 = __float_as_uint(ta[8 * 36]);
            unsigned a2 = __float_as_uint(ta[4]);
            unsigned a3 = __float_as_uint(ta[8 * 36 + 4]);
            const float* pb = phi_s + qr * 36 + kc * 8 + qc;
#pragma unroll
            for (int nt = 0; nt < 8; nt++) {
                unsigned b0 = __float_as_uint(pb[nt * 8 * 36]);
                unsigned b1 = __float_as_uint(pb[nt * 8 * 36 + 4]);
                mma_tf32(s[nt][0], s[nt][1], s[nt][2], s[nt][3],
                         a0, a1, a2, a3, b0, b1);
            }
        }

        // exp2 (rna-rounded) + rowsum of the rounded values
        unsigned p[8][4];
#pragma unroll
        for (int nt = 0; nt < 8; nt++) {
            unsigned e0 = cvt_tf32(ex2f(s[nt][0]));
            unsigned e1 = cvt_tf32(ex2f(s[nt][1]));
            unsigned e2 = cvt_tf32(ex2f(s[nt][2]));
            unsigned e3 = cvt_tf32(ex2f(s[nt][3]));
            l0 += __uint_as_float(e0) + __uint_as_float(e1);
            l1 += __uint_as_float(e2) + __uint_as_float(e3);
            p[nt][0] = e0; p[nt][1] = e1; p[nt][2] = e2; p[nt][3] = e3;
        }

        // GEMM2: O += P x g
#pragma unroll
        for (int ks = 0; ks < 8; ks++) {
            unsigned v00 = __shfl_sync(0xffffffffu, p[ks][0], srcA);
            unsigned v01 = __shfl_sync(0xffffffffu, p[ks][1], srcA);
            unsigned v10 = __shfl_sync(0xffffffffu, p[ks][2], srcA);
            unsigned v11 = __shfl_sync(0xffffffffu, p[ks][3], srcA);
            unsigned u00 = __shfl_sync(0xffffffffu, p[ks][0], srcB);
            unsigned u01 = __shfl_sync(0xffffffffu, p[ks][1], srcB);
            unsigned u10 = __shfl_sync(0xffffffffu, p[ks][2], srcB);
            unsigned u11 = __shfl_sync(0xffffffffu, p[ks][3], srcB);
            unsigned a0 = odd ? v01 : v00;
            unsigned a1 = odd ? v11 : v10;
            unsigned a2 = odd ? u01 : u00;
            unsigned a3 = odd ? u11 : u10;

            const float* gb = g_s + (ks * 8 + qc) * 136 + qr;
#pragma unroll
            for (int nt = 0; nt < 16; nt++) {
                unsigned b0 = __float_as_uint(gb[nt * 8]);
                unsigned b1 = __float_as_uint(gb[nt * 8 + 4 * 136]);
                mma_tf32(O[nt][0], O[nt][1], O[nt][2], O[nt][3],
                         a0, a1, a2, a3, b0, b1);
            }
        }
    }

    l0 += __shfl_xor_sync(0xffffffffu, l0, 1);
    l0 += __shfl_xor_sync(0xffffffffu, l0, 2);
    l1 += __shfl_xor_sync(0xffffffffu, l1, 1);
    l1 += __shfl_xor_sync(0xffffffffu, l1, 2);
    float inv0 = 1.0f / l0;
    float inv1 = 1.0f / l1;

    float* dst0 = d_att + ((size_t)b * N_ + row0) * C2_ + qc * 2;
#pragma unroll
    for (int nt = 0; nt < 16; nt++) {
        *(float2*)(dst0 + nt * 8) =
            make_float2(O[nt][0] * inv0, O[nt][1] * inv0);
        *(float2*)(dst0 + 8 * C2_ + nt * 8) =
            make_float2(O[nt][2] * inv1, O[nt][3] * inv1);
    }
}

// ============================================================================
// Kernel 3: out = w_o @ att + b_o + x via tf32 mma, split-att. (unchanged)
// ============================================================================
__global__ void __launch_bounds__(256) out_tc_kernel(
    const float* __restrict__ wo, const float* __restrict__ bo,
    const float* __restrict__ x, float* __restrict__ out) {
    extern __shared__ float sm[];
    float* w_s = sm;                // [32][132]
    float* ah  = sm + 32 * 132;     // [128][36]
    float* al  = ah + 128 * 36;     // [128][36]

    const int b  = blockIdx.y;
    const int Cbase = (blockIdx.x >> 5) * 32;
    const int N0    = (blockIdx.x & 31) * 128;
    const int tid  = threadIdx.x;
    const int wid  = tid >> 5, lane = tid & 31;
    const int m0   = (wid >> 2) * 16;
    const int n0w  = (wid & 3) * 32;
    const int qr = lane >> 2, qc = lane & 3;

#pragma unroll
    for (int i = 0; i < 16; i++) {
        int idx = i * 256 + tid;
        int r = idx >> 7, kk = idx & 127;
        w_s[r * 132 + kk] = cvt_tf32f(wo[(Cbase + r) * C2_ + kk]);
    }

    float acc[4][4];
#pragma unroll
    for (int nt = 0; nt < 4; nt++)
#pragma unroll
        for (int j = 0; j < 4; j++) acc[nt][j] = 0.f;

    for (int kp = 0; kp < 4; kp++) {
        const int k0 = kp * 32;
        __syncthreads();
#pragma unroll
        for (int i = 0; i < 4; i++) {
            int idx = i * 256 + tid;
            int nn = idx >> 3, kk4 = idx & 7;
            float4 v = *(const float4*)(
                d_att + ((size_t)b * N_ + N0 + nn) * C2_ + k0 + kk4 * 4);
            float4 h, l;
            h.x = cvt_tf32f(v.x); l.x = v.x - h.x;
            h.y = cvt_tf32f(v.y); l.y = v.y - h.y;
            h.z = cvt_tf32f(v.z); l.z = v.z - h.z;
            h.w = cvt_tf32f(v.w); l.w = v.w - h.w;
            *(float4*)(ah + nn * 36 + kk4 * 4) = h;
            *(float4*)(al + nn * 36 + kk4 * 4) = l;
        }
        __syncthreads();

#pragma unroll
        for (int ks = 0; ks < 4; ks++) {
            const float* wrow = w_s + (m0 + qr) * 132 + k0 + ks * 8 + qc;
            unsigned a0 = __float_as_uint(wrow[0]);
            unsigned a1 = __float_as_uint(wrow[8 * 132]);
            unsigned a2 = __float_as_uint(wrow[4]);
            unsigned a3 = __float_as_uint(wrow[8 * 132 + 4]);
#pragma unroll
            for (int nt = 0; nt < 4; nt++) {
                const float* bh = ah + (n0w + nt * 8 + qr) * 36 + ks * 8 + qc;
                const float* bl = al + (n0w + nt * 8 + qr) * 36 + ks * 8 + qc;
                unsigned b0 = __float_as_uint(bh[0]);
                unsigned b1 = __float_as_uint(bh[4]);
                mma_tf32(acc[nt][0], acc[nt][1], acc[nt][2], acc[nt][3],
                         a0, a1, a2, a3, b0, b1);
                unsigned c0 = __float_as_uint(bl[0]);
                unsigned c1 = __float_as_uint(bl[4]);
                mma_tf32(acc[nt][0], acc[nt][1], acc[nt][2], acc[nt][3],
                         a0, a1, a2, a3, c0, c1);
            }
        }
    }

#pragma unroll
    for (int rr = 0; rr < 2; rr++) {
        int c = Cbase + m0 + qr + rr * 8;
        float bias = bo[c];
#pragma unroll
        for (int nt = 0; nt < 4; nt++) {
            int n = N0 + n0w + qc * 2 + nt * 8;
            size_t idx = ((size_t)b * C_ + c) * N_ + n;
            float2 xv = *(const float2*)(x + idx);
            *(float2*)(out + idx) = make_float2(
                acc[nt][rr * 2] + bias + xv.x,
                acc[nt][rr * 2 + 1] + bias + xv.y);
        }
    }
}

// ============================================================================
extern "C" void kernel_launch(void* const* d_in, const int* in_sizes, int n_in,
                              void* d_out, int out_size) {
    (void)in_sizes; (void)n_in; (void)out_size;
    const float* x  = (const float*)d_in[0];
    const float* wt = (const float*)d_in[1];
    const float* bt = (const float*)d_in[2];
    const float* wp = (const float*)d_in[3];
    const float* bp = (const float*)d_in[4];
    const float* wg = (const float*)d_in[5];
    const float* bg = (const float*)d_in[6];
    const float* wo = (const float*)d_in[7];
    const float* bo = (const float*)d_in[8];
    float* out = (float*)d_out;

    const int smem_proj  = (32 * 36 + 2 * 32 * 264) * 4;        // 72192
    const int smem_flash = (2 * 64 * 36 + 64 * 136) * 4;        // 53248
    const int smem_out   = (32 * 132 + 2 * 128 * 36) * 4;       // 53760

    cudaFuncSetAttribute(proj_tc_kernel,
                         cudaFuncAttributeMaxDynamicSharedMemorySize, smem_proj);
    cudaFuncSetAttribute(flash_tc_kernel,
                         cudaFuncAttributeMaxDynamicSharedMemorySize, smem_flash);
    cudaFuncSetAttribute(out_tc_kernel,
                         cudaFuncAttributeMaxDynamicSharedMemorySize, smem_out);

    proj_tc_kernel<<<dim3(96, B_), 256, smem_proj>>>(x, wt, bt, wp, bp, wg, bg);
    flash_tc_kernel<<<dim3(N_ / 64, B_), 128, smem_flash>>>();
    out_tc_kernel<<<dim3(256, B_), 256, smem_out>>>(wo, bo, x, out);
}

// round 5
// speedup vs baseline: 1.0636x; 1.0636x over previous
#include <cuda_runtime.h>

// NonLocalAttention: B=4, C=256, H=W=64 -> N=4096, C8=32, C2=128
//   proj_tc_kernel : theta/phi/g projections, tf32 mma, split-x, N-tile 128
//   flash_tc_kernel: tf32 mma flash attention, c2-split (2 CTAs per q-tile)
//   out_tc_kernel  : w_o @ att + b_o + x, tf32 mma with split-att

#define B_ 4
#define C_ 256
#define N_ 4096
#define C8_ 32
#define C2_ 128

__device__ float d_theta[B_ * C8_ * N_];
__device__ float d_phi[B_ * C8_ * N_];
__device__ float d_g[(size_t)B_ * N_ * C2_];
__device__ float d_att[(size_t)B_ * N_ * C2_];

// ---- intrinsics ----
__device__ __forceinline__ unsigned cvt_tf32(float x) {
    unsigned r;
    asm("cvt.rna.tf32.f32 %0, %1;" : "=r"(r) : "f"(x));
    return r;
}
__device__ __forceinline__ float cvt_tf32f(float x) {
    return __uint_as_float(cvt_tf32(x));
}
__device__ __forceinline__ float ex2f(float x) {
    float r;
    asm("ex2.approx.f32 %0, %1;" : "=f"(r) : "f"(x));
    return r;
}
__device__ __forceinline__ void mma_tf32(
    float& c0, float& c1, float& c2, float& c3,
    unsigned a0, unsigned a1, unsigned a2, unsigned a3,
    unsigned b0, unsigned b1) {
    asm("mma.sync.aligned.m16n8k8.row.col.f32.tf32.tf32.f32 "
        "{%0,%1,%2,%3}, {%4,%5,%6,%7}, {%8,%9}, {%0,%1,%2,%3};"
        : "+f"(c0), "+f"(c1), "+f"(c2), "+f"(c3)
        : "r"(a0), "r"(a1), "r"(a2), "r"(a3), "r"(b0), "r"(b1));
}

// ============================================================================
// Kernel 1: projections via tf32 mma, split-x. N-tile = 128 (occupancy).
// CTA = 256 thr (8 warps: 2M x 4N). CTA tile: M=32 outs, N=128 px, K=256.
// Grid.x = 6 Mgroups * 32 Ngroups = 192, grid.y = B.
// ============================================================================
__global__ void __launch_bounds__(256) proj_tc_kernel(
    const float* __restrict__ x,
    const float* __restrict__ wt, const float* __restrict__ bt,
    const float* __restrict__ wp, const float* __restrict__ bp,
    const float* __restrict__ wg, const float* __restrict__ bg) {
    extern __shared__ float sm[];
    float* ws = sm;                 // [32][36]   tf32 weights (k-phase)
    float* xh = sm + 32 * 36;       // [32][136]  x hi
    float* xl = xh + 32 * 136;      // [32][136]  x lo

    const int b  = blockIdx.y;
    const int Mbase = (blockIdx.x >> 5) * 32;
    const int N0    = (blockIdx.x & 31) * 128;
    const int tid  = threadIdx.x;
    const int wid  = tid >> 5, lane = tid & 31;
    const int m0   = (wid >> 2) * 16;
    const int n0w  = (wid & 3) * 32;
    const int qr = lane >> 2, qc = lane & 3;

    float acc[4][4];
#pragma unroll
    for (int nt = 0; nt < 4; nt++)
#pragma unroll
        for (int j = 0; j < 4; j++) acc[nt][j] = 0.f;

    for (int kp = 0; kp < 8; kp++) {
        const int k0 = kp * 32;
        __syncthreads();
        // stage weights [32 o][32 k] -> tf32(rna)
#pragma unroll
        for (int i = 0; i < 4; i++) {
            int idx = i * 256 + tid;           // 0..1023
            int r = idx >> 5, kk = idx & 31;
            int o = Mbase + r;
            const float* src = (o < 32) ? wt + o * C_
                             : (o < 64) ? wp + (o - 32) * C_
                                        : wg + (o - 64) * C_;
            ws[r * 36 + kk] = cvt_tf32f(src[k0 + kk]);
        }
        // stage x [32 c][128 n], split hi/lo
#pragma unroll
        for (int i = 0; i < 4; i++) {
            int idx = i * 256 + tid;           // 0..1023
            int cc = idx >> 5, nn4 = idx & 31;
            float4 v = *(const float4*)(
                x + ((size_t)(b * C_ + k0 + cc)) * N_ + N0 + nn4 * 4);
            float4 h, l;
            h.x = cvt_tf32f(v.x); l.x = v.x - h.x;
            h.y = cvt_tf32f(v.y); l.y = v.y - h.y;
            h.z = cvt_tf32f(v.z); l.z = v.z - h.z;
            h.w = cvt_tf32f(v.w); l.w = v.w - h.w;
            *(float4*)(xh + cc * 136 + nn4 * 4) = h;
            *(float4*)(xl + cc * 136 + nn4 * 4) = l;
        }
        __syncthreads();

#pragma unroll
        for (int ks = 0; ks < 4; ks++) {
            const float* wrow = ws + (m0 + qr) * 36 + ks * 8 + qc;
            unsigned a0 = __float_as_uint(wrow[0]);
            unsigned a1 = __float_as_uint(wrow[8 * 36]);
            unsigned a2 = __float_as_uint(wrow[4]);
            unsigned a3 = __float_as_uint(wrow[8 * 36 + 4]);
            const float* bh = xh + (ks * 8 + qc) * 136 + n0w + qr;
            const float* bl = xl + (ks * 8 + qc) * 136 + n0w + qr;
#pragma unroll
            for (int nt = 0; nt < 4; nt++) {
                unsigned b0 = __float_as_uint(bh[nt * 8]);
                unsigned b1 = __float_as_uint(bh[4 * 136 + nt * 8]);
                mma_tf32(acc[nt][0], acc[nt][1], acc[nt][2], acc[nt][3],
                         a0, a1, a2, a3, b0, b1);
                unsigned l0 = __float_as_uint(bl[nt * 8]);
                unsigned l1 = __float_as_uint(bl[4 * 136 + nt * 8]);
                mma_tf32(acc[nt][0], acc[nt][1], acc[nt][2], acc[nt][3],
                         a0, a1, a2, a3, l0, l1);
            }
        }
    }

#pragma unroll
    for (int rr = 0; rr < 2; rr++) {
        int o = Mbase + m0 + qr + rr * 8;
        if (o < 32) {
            float bias = bt[o];
            float* dst = d_theta + ((size_t)b * C8_ + o) * N_ + N0 + n0w + qc * 2;
#pragma unroll
            for (int nt = 0; nt < 4; nt++)
                *(float2*)(dst + nt * 8) = make_float2(
                    acc[nt][rr * 2] + bias, acc[nt][rr * 2 + 1] + bias);
        } else if (o < 64) {
            float bias = bp[o - 32];
            float* dst = d_phi + ((size_t)b * C8_ + (o - 32)) * N_ + N0 + n0w + qc * 2;
#pragma unroll
            for (int nt = 0; nt < 4; nt++)
                *(float2*)(dst + nt * 8) = make_float2(
                    acc[nt][rr * 2] + bias, acc[nt][rr * 2 + 1] + bias);
        } else {
            int c2 = o - 64;
            float bias = bg[c2];
#pragma unroll
            for (int nt = 0; nt < 4; nt++) {
                int n = N0 + n0w + qc * 2 + nt * 8;
                d_g[((size_t)b * N_ + n) * C2_ + c2]     = acc[nt][rr * 2] + bias;
                d_g[((size_t)b * N_ + n + 1) * C2_ + c2] = acc[nt][rr * 2 + 1] + bias;
            }
        }
    }
}

// ============================================================================
// Kernel 2: tf32 flash attention, c2-split: blockIdx.z picks 64-col half.
// CTA = 128 thr. O regs halved (32/thread). GEMM1+softmax duplicated per half.
// ============================================================================
__global__ void __launch_bounds__(128, 3) flash_tc_kernel() {
    extern __shared__ float sm[];
    float* th_s  = sm;               // [64][36]  theta[q][c] * log2e (tf32)
    float* phi_s = sm + 64 * 36;     // [64][36]  phi[k][c]   (tf32)
    float* g_s   = sm + 2 * 64 * 36; // [64][72]  g[k][c2-half] (tf32)

    const int b   = blockIdx.y;
    const int q0  = blockIdx.x * 64;
    const int ch  = blockIdx.z;      // 0/1: which 64-col half of c2
    const int tid = threadIdx.x;
    const int w    = tid >> 5;
    const int lane = tid & 31;
    const int qr = lane >> 2;
    const int qc = lane & 3;
    const int row0 = q0 + w * 16 + qr;

    const float LOG2E = 1.4426950408889634f;
    for (int idx = tid; idx < 2048; idx += 128) {
        int c = idx >> 6, q = idx & 63;
        th_s[q * 36 + c] =
            cvt_tf32f(d_theta[((size_t)b * C8_ + c) * N_ + q0 + q] * LOG2E);
    }

    float O[8][4];
#pragma unroll
    for (int nt = 0; nt < 8; nt++)
#pragma unroll
        for (int j = 0; j < 4; j++) O[nt][j] = 0.f;
    float l0 = 0.f, l1 = 0.f;

    const int srcA = (lane & ~3) | ((lane & 3) >> 1);
    const int srcB = srcA + 2;
    const bool odd = lane & 1;

    for (int kt = 0; kt < N_; kt += 64) {
        __syncthreads();
        // stage phi tile [64][32]
#pragma unroll
        for (int it = 0; it < 16; it++) {
            int idx = it * 128 + tid;
            int c = idx >> 6, k = idx & 63;
            phi_s[k * 36 + c] =
                cvt_tf32f(d_phi[((size_t)b * C8_ + c) * N_ + kt + k]);
        }
        // stage g half-tile [64][64]
#pragma unroll
        for (int it = 0; it < 8; it++) {
            int idx = it * 128 + tid;
            int k = idx >> 4, c4 = idx & 15;
            float4 v = *(const float4*)(
                d_g + ((size_t)b * N_ + kt + k) * C2_ + ch * 64 + c4 * 4);
            v.x = cvt_tf32f(v.x); v.y = cvt_tf32f(v.y);
            v.z = cvt_tf32f(v.z); v.w = cvt_tf32f(v.w);
            *(float4*)(g_s + k * 72 + c4 * 4) = v;
        }
        __syncthreads();

        // GEMM1: S = theta x phi^T
        float s[8][4];
#pragma unroll
        for (int nt = 0; nt < 8; nt++)
#pragma unroll
            for (int j = 0; j < 4; j++) s[nt][j] = 0.f;

#pragma unroll
        for (int kc = 0; kc < 4; kc++) {
            const float* ta = th_s + (w * 16 + qr) * 36 + kc * 8 + qc;
            unsigned a0 = __float_as_uint(ta[0]);
            unsigned a1 = __float_as_uint(ta[8 * 36]);
            unsigned a2 = __float_as_uint(ta[4]);
            unsigned a3 = __float_as_uint(ta[8 * 36 + 4]);
            const float* pb = phi_s + qr * 36 + kc * 8 + qc;
#pragma unroll
            for (int nt = 0; nt < 8; nt++) {
                unsigned b0 = __float_as_uint(pb[nt * 8 * 36]);
                unsigned b1 = __float_as_uint(pb[nt * 8 * 36 + 4]);
                mma_tf32(s[nt][0], s[nt][1], s[nt][2], s[nt][3],
                         a0, a1, a2, a3, b0, b1);
            }
        }

        // exp2 (rna-rounded) + rowsum of the rounded values
        unsigned p[8][4];
#pragma unroll
        for (int nt = 0; nt < 8; nt++) {
            unsigned e0 = cvt_tf32(ex2f(s[nt][0]));
            unsigned e1 = cvt_tf32(ex2f(s[nt][1]));
            unsigned e2 = cvt_tf32(ex2f(s[nt][2]));
            unsigned e3 = cvt_tf32(ex2f(s[nt][3]));
            l0 += __uint_as_float(e0) + __uint_as_float(e1);
            l1 += __uint_as_float(e2) + __uint_as_float(e3);
            p[nt][0] = e0; p[nt][1] = e1; p[nt][2] = e2; p[nt][3] = e3;
        }

        // GEMM2: O += P x g(half)
#pragma unroll
        for (int ks = 0; ks < 8; ks++) {
            unsigned v00 = __shfl_sync(0xffffffffu, p[ks][0], srcA);
            unsigned v01 = __shfl_sync(0xffffffffu, p[ks][1], srcA);
            unsigned v10 = __shfl_sync(0xffffffffu, p[ks][2], srcA);
            unsigned v11 = __shfl_sync(0xffffffffu, p[ks][3], srcA);
            unsigned u00 = __shfl_sync(0xffffffffu, p[ks][0], srcB);
            unsigned u01 = __shfl_sync(0xffffffffu, p[ks][1], srcB);
            unsigned u10 = __shfl_sync(0xffffffffu, p[ks][2], srcB);
            unsigned u11 = __shfl_sync(0xffffffffu, p[ks][3], srcB);
            unsigned a0 = odd ? v01 : v00;
            unsigned a1 = odd ? v11 : v10;
            unsigned a2 = odd ? u01 : u00;
            unsigned a3 = odd ? u11 : u10;

            const float* gb = g_s + (ks * 8 + qc) * 72 + qr;
#pragma unroll
            for (int nt = 0; nt < 8; nt++) {
                unsigned b0 = __float_as_uint(gb[nt * 8]);
                unsigned b1 = __float_as_uint(gb[nt * 8 + 4 * 72]);
                mma_tf32(O[nt][0], O[nt][1], O[nt][2], O[nt][3],
                         a0, a1, a2, a3, b0, b1);
            }
        }
    }

    l0 += __shfl_xor_sync(0xffffffffu, l0, 1);
    l0 += __shfl_xor_sync(0xffffffffu, l0, 2);
    l1 += __shfl_xor_sync(0xffffffffu, l1, 1);
    l1 += __shfl_xor_sync(0xffffffffu, l1, 2);
    float inv0 = 1.0f / l0;
    float inv1 = 1.0f / l1;

    float* dst0 = d_att + ((size_t)b * N_ + row0) * C2_ + ch * 64 + qc * 2;
#pragma unroll
    for (int nt = 0; nt < 8; nt++) {
        *(float2*)(dst0 + nt * 8) =
            make_float2(O[nt][0] * inv0, O[nt][1] * inv0);
        *(float2*)(dst0 + 8 * C2_ + nt * 8) =
            make_float2(O[nt][2] * inv1, O[nt][3] * inv1);
    }
}

// ============================================================================
// Kernel 3: out = w_o @ att + b_o + x via tf32 mma, split-att. (unchanged)
// ============================================================================
__global__ void __launch_bounds__(256) out_tc_kernel(
    const float* __restrict__ wo, const float* __restrict__ bo,
    const float* __restrict__ x, float* __restrict__ out) {
    extern __shared__ float sm[];
    float* w_s = sm;                // [32][132]
    float* ah  = sm + 32 * 132;     // [128][36]
    float* al  = ah + 128 * 36;     // [128][36]

    const int b  = blockIdx.y;
    const int Cbase = (blockIdx.x >> 5) * 32;
    const int N0    = (blockIdx.x & 31) * 128;
    const int tid  = threadIdx.x;
    const int wid  = tid >> 5, lane = tid & 31;
    const int m0   = (wid >> 2) * 16;
    const int n0w  = (wid & 3) * 32;
    const int qr = lane >> 2, qc = lane & 3;

#pragma unroll
    for (int i = 0; i < 16; i++) {
        int idx = i * 256 + tid;
        int r = idx >> 7, kk = idx & 127;
        w_s[r * 132 + kk] = cvt_tf32f(wo[(Cbase + r) * C2_ + kk]);
    }

    float acc[4][4];
#pragma unroll
    for (int nt = 0; nt < 4; nt++)
#pragma unroll
        for (int j = 0; j < 4; j++) acc[nt][j] = 0.f;

    for (int kp = 0; kp < 4; kp++) {
        const int k0 = kp * 32;
        __syncthreads();
#pragma unroll
        for (int i = 0; i < 4; i++) {
            int idx = i * 256 + tid;
            int nn = idx >> 3, kk4 = idx & 7;
            float4 v = *(const float4*)(
                d_att + ((size_t)b * N_ + N0 + nn) * C2_ + k0 + kk4 * 4);
            float4 h, l;
            h.x = cvt_tf32f(v.x); l.x = v.x - h.x;
            h.y = cvt_tf32f(v.y); l.y = v.y - h.y;
            h.z = cvt_tf32f(v.z); l.z = v.z - h.z;
            h.w = cvt_tf32f(v.w); l.w = v.w - h.w;
            *(float4*)(ah + nn * 36 + kk4 * 4) = h;
            *(float4*)(al + nn * 36 + kk4 * 4) = l;
        }
        __syncthreads();

#pragma unroll
        for (int ks = 0; ks < 4; ks++) {
            const float* wrow = w_s + (m0 + qr) * 132 + k0 + ks * 8 + qc;
            unsigned a0 = __float_as_uint(wrow[0]);
            unsigned a1 = __float_as_uint(wrow[8 * 132]);
            unsigned a2 = __float_as_uint(wrow[4]);
            unsigned a3 = __float_as_uint(wrow[8 * 132 + 4]);
#pragma unroll
            for (int nt = 0; nt < 4; nt++) {
                const float* bh = ah + (n0w + nt * 8 + qr) * 36 + ks * 8 + qc;
                const float* bl = al + (n0w + nt * 8 + qr) * 36 + ks * 8 + qc;
                unsigned b0 = __float_as_uint(bh[0]);
                unsigned b1 = __float_as_uint(bh[4]);
                mma_tf32(acc[nt][0], acc[nt][1], acc[nt][2], acc[nt][3],
                         a0, a1, a2, a3, b0, b1);
                unsigned c0 = __float_as_uint(bl[0]);
                unsigned c1 = __float_as_uint(bl[4]);
                mma_tf32(acc[nt][0], acc[nt][1], acc[nt][2], acc[nt][3],
                         a0, a1, a2, a3, c0, c1);
            }
        }
    }

#pragma unroll
    for (int rr = 0; rr < 2; rr++) {
        int c = Cbase + m0 + qr + rr * 8;
        float bias = bo[c];
#pragma unroll
        for (int nt = 0; nt < 4; nt++) {
            int n = N0 + n0w + qc * 2 + nt * 8;
            size_t idx = ((size_t)b * C_ + c) * N_ + n;
            float2 xv = *(const float2*)(x + idx);
            *(float2*)(out + idx) = make_float2(
                acc[nt][rr * 2] + bias + xv.x,
                acc[nt][rr * 2 + 1] + bias + xv.y);
        }
    }
}

// ============================================================================
extern "C" void kernel_launch(void* const* d_in, const int* in_sizes, int n_in,
                              void* d_out, int out_size) {
    (void)in_sizes; (void)n_in; (void)out_size;
    const float* x  = (const float*)d_in[0];
    const float* wt = (const float*)d_in[1];
    const float* bt = (const float*)d_in[2];
    const float* wp = (const float*)d_in[3];
    const float* bp = (const float*)d_in[4];
    const float* wg = (const float*)d_in[5];
    const float* bg = (const float*)d_in[6];
    const float* wo = (const float*)d_in[7];
    const float* bo = (const float*)d_in[8];
    float* out = (float*)d_out;

    const int smem_proj  = (32 * 36 + 2 * 32 * 136) * 4;        // 39424
    const int smem_flash = (2 * 64 * 36 + 64 * 72) * 4;         // 36864
    const int smem_out   = (32 * 132 + 2 * 128 * 36) * 4;       // 53760

    cudaFuncSetAttribute(proj_tc_kernel,
                         cudaFuncAttributeMaxDynamicSharedMemorySize, smem_proj);
    cudaFuncSetAttribute(flash_tc_kernel,
                         cudaFuncAttributeMaxDynamicSharedMemorySize, smem_flash);
    cudaFuncSetAttribute(out_tc_kernel,
                         cudaFuncAttributeMaxDynamicSharedMemorySize, smem_out);

    proj_tc_kernel<<<dim3(192, B_), 256, smem_proj>>>(x, wt, bt, wp, bp, wg, bg);
    flash_tc_kernel<<<dim3(N_ / 64, B_, 2), 128, smem_flash>>>();
    out_tc_kernel<<<dim3(256, B_), 256, smem_out>>>(wo, bo, x, out);
}

// round 8
// speedup vs baseline: 1.3859x; 1.3029x over previous
#include <cuda_runtime.h>

// NonLocalAttention: B=4, C=256, H=W=64 -> N=4096, C8=32, C2=128
//   proj_tc_kernel : theta/phi/g projections (tf32 mma, split-x)
//   flash_tc_kernel: tf32 mma flash attention, KEY-SPLIT x2 (additive partials,
//                    unnormalized exp softmax -> partial O and l per half)
//   out_tc_kernel  : combines halves ((O1+O2)/(l1+l2)), then w_o @ att + b_o + x

#define B_ 4
#define C_ 256
#define N_ 4096
#define C8_ 32
#define C2_ 128

__device__ float d_theta[B_ * C8_ * N_];
__device__ float d_phi[B_ * C8_ * N_];
__device__ float d_g[(size_t)B_ * N_ * C2_];
__device__ float d_att[(size_t)2 * B_ * N_ * C2_];   // [half][b][n][c2], unnormalized
__device__ float d_l[(size_t)2 * B_ * N_];           // [half][b][n] row sums

// ---- intrinsics ----
__device__ __forceinline__ unsigned cvt_tf32(float x) {
    unsigned r;
    asm("cvt.rna.tf32.f32 %0, %1;" : "=r"(r) : "f"(x));
    return r;
}
__device__ __forceinline__ float cvt_tf32f(float x) {
    return __uint_as_float(cvt_tf32(x));
}
__device__ __forceinline__ float ex2f(float x) {
    float r;
    asm("ex2.approx.f32 %0, %1;" : "=f"(r) : "f"(x));
    return r;
}
__device__ __forceinline__ void mma_tf32(
    float& c0, float& c1, float& c2, float& c3,
    unsigned a0, unsigned a1, unsigned a2, unsigned a3,
    unsigned b0, unsigned b1) {
    asm("mma.sync.aligned.m16n8k8.row.col.f32.tf32.tf32.f32 "
        "{%0,%1,%2,%3}, {%4,%5,%6,%7}, {%8,%9}, {%0,%1,%2,%3};"
        : "+f"(c0), "+f"(c1), "+f"(c2), "+f"(c3)
        : "r"(a0), "r"(a1), "r"(a2), "r"(a3), "r"(b0), "r"(b1));
}

// ============================================================================
// Kernel 1: projections via tf32 mma, split-x. N-tile = 128.
// ============================================================================
__global__ void __launch_bounds__(256) proj_tc_kernel(
    const float* __restrict__ x,
    const float* __restrict__ wt, const float* __restrict__ bt,
    const float* __restrict__ wp, const float* __restrict__ bp,
    const float* __restrict__ wg, const float* __restrict__ bg) {
    extern __shared__ float sm[];
    float* ws = sm;                 // [32][36]
    float* xh = sm + 32 * 36;       // [32][136]
    float* xl = xh + 32 * 136;      // [32][136]

    const int b  = blockIdx.y;
    const int Mbase = (blockIdx.x >> 5) * 32;
    const int N0    = (blockIdx.x & 31) * 128;
    const int tid  = threadIdx.x;
    const int wid  = tid >> 5, lane = tid & 31;
    const int m0   = (wid >> 2) * 16;
    const int n0w  = (wid & 3) * 32;
    const int qr = lane >> 2, qc = lane & 3;

    float acc[4][4];
#pragma unroll
    for (int nt = 0; nt < 4; nt++)
#pragma unroll
        for (int j = 0; j < 4; j++) acc[nt][j] = 0.f;

    for (int kp = 0; kp < 8; kp++) {
        const int k0 = kp * 32;
        __syncthreads();
#pragma unroll
        for (int i = 0; i < 4; i++) {
            int idx = i * 256 + tid;
            int r = idx >> 5, kk = idx & 31;
            int o = Mbase + r;
            const float* src = (o < 32) ? wt + o * C_
                             : (o < 64) ? wp + (o - 32) * C_
                                        : wg + (o - 64) * C_;
            ws[r * 36 + kk] = cvt_tf32f(src[k0 + kk]);
        }
#pragma unroll
        for (int i = 0; i < 4; i++) {
            int idx = i * 256 + tid;
            int cc = idx >> 5, nn4 = idx & 31;
            float4 v = *(const float4*)(
                x + ((size_t)(b * C_ + k0 + cc)) * N_ + N0 + nn4 * 4);
            float4 h, l;
            h.x = cvt_tf32f(v.x); l.x = v.x - h.x;
            h.y = cvt_tf32f(v.y); l.y = v.y - h.y;
            h.z = cvt_tf32f(v.z); l.z = v.z - h.z;
            h.w = cvt_tf32f(v.w); l.w = v.w - h.w;
            *(float4*)(xh + cc * 136 + nn4 * 4) = h;
            *(float4*)(xl + cc * 136 + nn4 * 4) = l;
        }
        __syncthreads();

#pragma unroll
        for (int ks = 0; ks < 4; ks++) {
            const float* wrow = ws + (m0 + qr) * 36 + ks * 8 + qc;
            unsigned a0 = __float_as_uint(wrow[0]);
            unsigned a1 = __float_as_uint(wrow[8 * 36]);
            unsigned a2 = __float_as_uint(wrow[4]);
            unsigned a3 = __float_as_uint(wrow[8 * 36 + 4]);
            const float* bh = xh + (ks * 8 + qc) * 136 + n0w + qr;
            const float* bl = xl + (ks * 8 + qc) * 136 + n0w + qr;
#pragma unroll
            for (int nt = 0; nt < 4; nt++) {
                unsigned b0 = __float_as_uint(bh[nt * 8]);
                unsigned b1 = __float_as_uint(bh[4 * 136 + nt * 8]);
                mma_tf32(acc[nt][0], acc[nt][1], acc[nt][2], acc[nt][3],
                         a0, a1, a2, a3, b0, b1);
                unsigned l0 = __float_as_uint(bl[nt * 8]);
                unsigned l1 = __float_as_uint(bl[4 * 136 + nt * 8]);
                mma_tf32(acc[nt][0], acc[nt][1], acc[nt][2], acc[nt][3],
                         a0, a1, a2, a3, l0, l1);
            }
        }
    }

#pragma unroll
    for (int rr = 0; rr < 2; rr++) {
        int o = Mbase + m0 + qr + rr * 8;
        if (o < 32) {
            float bias = bt[o];
            float* dst = d_theta + ((size_t)b * C8_ + o) * N_ + N0 + n0w + qc * 2;
#pragma unroll
            for (int nt = 0; nt < 4; nt++)
                *(float2*)(dst + nt * 8) = make_float2(
                    acc[nt][rr * 2] + bias, acc[nt][rr * 2 + 1] + bias);
        } else if (o < 64) {
            float bias = bp[o - 32];
            float* dst = d_phi + ((size_t)b * C8_ + (o - 32)) * N_ + N0 + n0w + qc * 2;
#pragma unroll
            for (int nt = 0; nt < 4; nt++)
                *(float2*)(dst + nt * 8) = make_float2(
                    acc[nt][rr * 2] + bias, acc[nt][rr * 2 + 1] + bias);
        } else {
            int c2 = o - 64;
            float bias = bg[c2];
#pragma unroll
            for (int nt = 0; nt < 4; nt++) {
                int n = N0 + n0w + qc * 2 + nt * 8;
                d_g[((size_t)b * N_ + n) * C2_ + c2]     = acc[nt][rr * 2] + bias;
                d_g[((size_t)b * N_ + n + 1) * C2_ + c2] = acc[nt][rr * 2 + 1] + bias;
            }
        }
    }
}

// ============================================================================
// Kernel 2: tf32 flash attention, key-split: blockIdx.z = key half (2048 keys).
// Stores UNNORMALIZED partial O and partial row-sum l.
// ============================================================================
__global__ void __launch_bounds__(128, 2) flash_tc_kernel() {
    extern __shared__ float sm[];
    float* phi_s = sm;              // [64][36]  phi[k][c]
    float* g_s   = sm + 64 * 36;    // [64][136] g[k][c2]

    const int b   = blockIdx.y;
    const int q0  = blockIdx.x * 64;
    const int hf  = blockIdx.z;     // key half
    const int tid = threadIdx.x;
    const int w    = tid >> 5;
    const int lane = tid & 31;
    const int qr = lane >> 2;
    const int qc = lane & 3;
    const int row0 = q0 + w * 16 + qr;

    const float LOG2E = 1.4426950408889634f;
    unsigned at[4][4];
    {
        const float* tp = d_theta + (size_t)b * C8_ * N_;
#pragma unroll
        for (int kc = 0; kc < 4; kc++) {
            int c = kc * 8 + qc;
            at[kc][0] = cvt_tf32(tp[(size_t)c * N_ + row0] * LOG2E);
            at[kc][1] = cvt_tf32(tp[(size_t)c * N_ + row0 + 8] * LOG2E);
            at[kc][2] = cvt_tf32(tp[(size_t)(c + 4) * N_ + row0] * LOG2E);
            at[kc][3] = cvt_tf32(tp[(size_t)(c + 4) * N_ + row0 + 8] * LOG2E);
        }
    }

    float O[16][4];
#pragma unroll
    for (int nt = 0; nt < 16; nt++)
#pragma unroll
        for (int j = 0; j < 4; j++) O[nt][j] = 0.f;
    float l0 = 0.f, l1 = 0.f;

    const int srcA = (lane & ~3) | ((lane & 3) >> 1);
    const int srcB = srcA + 2;
    const bool odd = lane & 1;

    const int ktbeg = hf * (N_ / 2);
    const int ktend = ktbeg + (N_ / 2);
    for (int kt = ktbeg; kt < ktend; kt += 64) {
        __syncthreads();
#pragma unroll
        for (int it = 0; it < 16; it++) {
            int idx = it * 128 + tid;
            int c = idx >> 6, k = idx & 63;
            phi_s[k * 36 + c] =
                cvt_tf32f(d_phi[((size_t)b * C8_ + c) * N_ + kt + k]);
        }
        {
            const float4* gg = (const float4*)(d_g + ((size_t)b * N_ + kt) * C2_);
#pragma unroll
            for (int it = 0; it < 16; it++) {
                int idx = it * 128 + tid;
                int k = idx >> 5, c4 = idx & 31;
                float4 v = gg[idx];
                v.x = cvt_tf32f(v.x); v.y = cvt_tf32f(v.y);
                v.z = cvt_tf32f(v.z); v.w = cvt_tf32f(v.w);
                *(float4*)(g_s + k * 136 + c4 * 4) = v;
            }
        }
        __syncthreads();

        // GEMM1: S = theta x phi^T
        float s[8][4];
#pragma unroll
        for (int nt = 0; nt < 8; nt++)
#pragma unroll
            for (int j = 0; j < 4; j++) s[nt][j] = 0.f;

#pragma unroll
        for (int kc = 0; kc < 4; kc++) {
            const float* pb = phi_s + qr * 36 + kc * 8 + qc;
#pragma unroll
            for (int nt = 0; nt < 8; nt++) {
                unsigned b0 = __float_as_uint(pb[nt * 8 * 36]);
                unsigned b1 = __float_as_uint(pb[nt * 8 * 36 + 4]);
                mma_tf32(s[nt][0], s[nt][1], s[nt][2], s[nt][3],
                         at[kc][0], at[kc][1], at[kc][2], at[kc][3], b0, b1);
            }
        }

        // exp2 (rna-rounded) + rowsum of the rounded values
        unsigned p[8][4];
#pragma unroll
        for (int nt = 0; nt < 8; nt++) {
            unsigned e0 = cvt_tf32(ex2f(s[nt][0]));
            unsigned e1 = cvt_tf32(ex2f(s[nt][1]));
            unsigned e2 = cvt_tf32(ex2f(s[nt][2]));
            unsigned e3 = cvt_tf32(ex2f(s[nt][3]));
            l0 += __uint_as_float(e0) + __uint_as_float(e1);
            l1 += __uint_as_float(e2) + __uint_as_float(e3);
            p[nt][0] = e0; p[nt][1] = e1; p[nt][2] = e2; p[nt][3] = e3;
        }

        // GEMM2: O += P x g
#pragma unroll
        for (int ks = 0; ks < 8; ks++) {
            unsigned v00 = __shfl_sync(0xffffffffu, p[ks][0], srcA);
            unsigned v01 = __shfl_sync(0xffffffffu, p[ks][1], srcA);
            unsigned v10 = __shfl_sync(0xffffffffu, p[ks][2], srcA);
            unsigned v11 = __shfl_sync(0xffffffffu, p[ks][3], srcA);
            unsigned u00 = __shfl_sync(0xffffffffu, p[ks][0], srcB);
            unsigned u01 = __shfl_sync(0xffffffffu, p[ks][1], srcB);
            unsigned u10 = __shfl_sync(0xffffffffu, p[ks][2], srcB);
            unsigned u11 = __shfl_sync(0xffffffffu, p[ks][3], srcB);
            unsigned a0 = odd ? v01 : v00;
            unsigned a1 = odd ? v11 : v10;
            unsigned a2 = odd ? u01 : u00;
            unsigned a3 = odd ? u11 : u10;

            const float* gb = g_s + (ks * 8 + qc) * 136 + qr;
#pragma unroll
            for (int nt = 0; nt < 16; nt++) {
                unsigned b0 = __float_as_uint(gb[nt * 8]);
                unsigned b1 = __float_as_uint(gb[nt * 8 + 4 * 136]);
                mma_tf32(O[nt][0], O[nt][1], O[nt][2], O[nt][3],
                         a0, a1, a2, a3, b0, b1);
            }
        }
    }

    // reduce partial l within quads; store unnormalized partials
    l0 += __shfl_xor_sync(0xffffffffu, l0, 1);
    l0 += __shfl_xor_sync(0xffffffffu, l0, 2);
    l1 += __shfl_xor_sync(0xffffffffu, l1, 1);
    l1 += __shfl_xor_sync(0xffffffffu, l1, 2);
    if (qc == 0) {
        d_l[((size_t)hf * B_ + b) * N_ + row0]     = l0;
        d_l[((size_t)hf * B_ + b) * N_ + row0 + 8] = l1;
    }

    float* dst0 = d_att + (((size_t)hf * B_ + b) * N_ + row0) * C2_ + qc * 2;
#pragma unroll
    for (int nt = 0; nt < 16; nt++) {
        *(float2*)(dst0 + nt * 8) = make_float2(O[nt][0], O[nt][1]);
        *(float2*)(dst0 + 8 * C2_ + nt * 8) = make_float2(O[nt][2], O[nt][3]);
    }
}

// ============================================================================
// Kernel 3: out = w_o @ ((O1+O2)/(l1+l2)) + b_o + x via tf32 mma, split-att.
// ============================================================================
__global__ void __launch_bounds__(256) out_tc_kernel(
    const float* __restrict__ wo, const float* __restrict__ bo,
    const float* __restrict__ x, float* __restrict__ out) {
    extern __shared__ float sm[];
    float* w_s  = sm;                 // [32][132]
    float* ah   = sm + 32 * 132;      // [128][36]
    float* al   = ah + 128 * 36;      // [128][36]
    float* lrow = al + 128 * 36;      // [128] 1/(l1+l2)

    const int b  = blockIdx.y;
    const int Cbase = (blockIdx.x >> 5) * 32;
    const int N0    = (blockIdx.x & 31) * 128;
    const int tid  = threadIdx.x;
    const int wid  = tid >> 5, lane = tid & 31;
    const int m0   = (wid >> 2) * 16;
    const int n0w  = (wid & 3) * 32;
    const int qr = lane >> 2, qc = lane & 3;

#pragma unroll
    for (int i = 0; i < 16; i++) {
        int idx = i * 256 + tid;
        int r = idx >> 7, kk = idx & 127;
        w_s[r * 132 + kk] = cvt_tf32f(wo[(Cbase + r) * C2_ + kk]);
    }
    if (tid < 128) {
        size_t n = (size_t)b * N_ + N0 + tid;
        lrow[tid] = 1.0f / (d_l[n] + d_l[(size_t)B_ * N_ + n]);
    }

    float acc[4][4];
#pragma unroll
    for (int nt = 0; nt < 4; nt++)
#pragma unroll
        for (int j = 0; j < 4; j++) acc[nt][j] = 0.f;

    const size_t halfoff = (size_t)B_ * N_ * C2_;
    for (int kp = 0; kp < 4; kp++) {
        const int k0 = kp * 32;
        __syncthreads();
#pragma unroll
        for (int i = 0; i < 4; i++) {
            int idx = i * 256 + tid;
            int nn = idx >> 3, kk4 = idx & 7;
            size_t base = ((size_t)b * N_ + N0 + nn) * C2_ + k0 + kk4 * 4;
            float4 v1 = *(const float4*)(d_att + base);
            float4 v2 = *(const float4*)(d_att + halfoff + base);
            float inv = lrow[nn];
            float4 v;
            v.x = (v1.x + v2.x) * inv;
            v.y = (v1.y + v2.y) * inv;
            v.z = (v1.z + v2.z) * inv;
            v.w = (v1.w + v2.w) * inv;
            float4 h, l;
            h.x = cvt_tf32f(v.x); l.x = v.x - h.x;
            h.y = cvt_tf32f(v.y); l.y = v.y - h.y;
            h.z = cvt_tf32f(v.z); l.z = v.z - h.z;
            h.w = cvt_tf32f(v.w); l.w = v.w - h.w;
            *(float4*)(ah + nn * 36 + kk4 * 4) = h;
            *(float4*)(al + nn * 36 + kk4 * 4) = l;
        }
        __syncthreads();

#pragma unroll
        for (int ks = 0; ks < 4; ks++) {
            const float* wrow = w_s + (m0 + qr) * 132 + k0 + ks * 8 + qc;
            unsigned a0 = __float_as_uint(wrow[0]);
            unsigned a1 = __float_as_uint(wrow[8 * 132]);
            unsigned a2 = __float_as_uint(wrow[4]);
            unsigned a3 = __float_as_uint(wrow[8 * 132 + 4]);
#pragma unroll
            for (int nt = 0; nt < 4; nt++) {
                const float* bh = ah + (n0w + nt * 8 + qr) * 36 + ks * 8 + qc;
                const float* bl = al + (n0w + nt * 8 + qr) * 36 + ks * 8 + qc;
                unsigned b0 = __float_as_uint(bh[0]);
                unsigned b1 = __float_as_uint(bh[4]);
                mma_tf32(acc[nt][0], acc[nt][1], acc[nt][2], acc[nt][3],
                         a0, a1, a2, a3, b0, b1);
                unsigned c0 = __float_as_uint(bl[0]);
                unsigned c1 = __float_as_uint(bl[4]);
                mma_tf32(acc[nt][0], acc[nt][1], acc[nt][2], acc[nt][3],
                         a0, a1, a2, a3, c0, c1);
            }
        }
    }

#pragma unroll
    for (int rr = 0; rr < 2; rr++) {
        int c = Cbase + m0 + qr + rr * 8;
        float bias = bo[c];
#pragma unroll
        for (int nt = 0; nt < 4; nt++) {
            int n = N0 + n0w + qc * 2 + nt * 8;
            size_t idx = ((size_t)b * C_ + c) * N_ + n;
            float2 xv = *(const float2*)(x + idx);
            *(float2*)(out + idx) = make_float2(
                acc[nt][rr * 2] + bias + xv.x,
                acc[nt][rr * 2 + 1] + bias + xv.y);
        }
    }
}

// ============================================================================
extern "C" void kernel_launch(void* const* d_in, const int* in_sizes, int n_in,
                              void* d_out, int out_size) {
    (void)in_sizes; (void)n_in; (void)out_size;
    const float* x  = (const float*)d_in[0];
    const float* wt = (const float*)d_in[1];
    const float* bt = (const float*)d_in[2];
    const float* wp = (const float*)d_in[3];
    const float* bp = (const float*)d_in[4];
    const float* wg = (const float*)d_in[5];
    const float* bg = (const float*)d_in[6];
    const float* wo = (const float*)d_in[7];
    const float* bo = (const float*)d_in[8];
    float* out = (float*)d_out;

    const int smem_proj  = (32 * 36 + 2 * 32 * 136) * 4;         // 39424
    const int smem_flash = (64 * 36 + 64 * 136) * 4;             // 44032
    const int smem_out   = (32 * 132 + 2 * 128 * 36 + 128) * 4;  // 54272

    cudaFuncSetAttribute(proj_tc_kernel,
                         cudaFuncAttributeMaxDynamicSharedMemorySize, smem_proj);
    cudaFuncSetAttribute(flash_tc_kernel,
                         cudaFuncAttributeMaxDynamicSharedMemorySize, smem_flash);
    cudaFuncSetAttribute(out_tc_kernel,
                         cudaFuncAttributeMaxDynamicSharedMemorySize, smem_out);

    proj_tc_kernel<<<dim3(192, B_), 256, smem_proj>>>(x, wt, bt, wp, bp, wg, bg);
    flash_tc_kernel<<<dim3(N_ / 64, B_, 2), 128, smem_flash>>>();
    out_tc_kernel<<<dim3(256, B_), 256, smem_out>>>(wo, bo, x, out);
}

// round 9
// speedup vs baseline: 1.9368x; 1.3975x over previous
#include <cuda_runtime.h>
#include <cuda_fp16.h>

// NonLocalAttention: B=4, C=256, H=W=64 -> N=4096, C8=32, C2=128
//   proj_tc_kernel : theta/phi/g projections (tf32 mma, split-x)
//                    outputs fp16: theta(*log2e)[b][c][n], phi[b][c][n],
//                    g[b][c2][n] (transposed)
//   flash_tc_kernel: fp16 m16n8k16 flash attention, online-max softmax,
//                    P stays in registers (C-layout == next A-layout)
//   out_tc_kernel  : w_o @ att + b_o + x (tf32 mma, split-att)

#define B_ 4
#define C_ 256
#define N_ 4096
#define C8_ 32
#define C2_ 128

__device__ __half d_theta[(size_t)B_ * C8_ * N_];   // theta * log2e
__device__ __half d_phi[(size_t)B_ * C8_ * N_];
__device__ __half d_g[(size_t)B_ * C2_ * N_];       // [b][c2][n]
__device__ float  d_att[(size_t)B_ * N_ * C2_];

// ---- intrinsics ----
__device__ __forceinline__ unsigned cvt_tf32(float x) {
    unsigned r;
    asm("cvt.rna.tf32.f32 %0, %1;" : "=r"(r) : "f"(x));
    return r;
}
__device__ __forceinline__ float cvt_tf32f(float x) {
    return __uint_as_float(cvt_tf32(x));
}
__device__ __forceinline__ float ex2f(float x) {
    float r;
    asm("ex2.approx.f32 %0, %1;" : "=f"(r) : "f"(x));
    return r;
}
__device__ __forceinline__ void mma_tf32(
    float& c0, float& c1, float& c2, float& c3,
    unsigned a0, unsigned a1, unsigned a2, unsigned a3,
    unsigned b0, unsigned b1) {
    asm("mma.sync.aligned.m16n8k8.row.col.f32.tf32.tf32.f32 "
        "{%0,%1,%2,%3}, {%4,%5,%6,%7}, {%8,%9}, {%0,%1,%2,%3};"
        : "+f"(c0), "+f"(c1), "+f"(c2), "+f"(c3)
        : "r"(a0), "r"(a1), "r"(a2), "r"(a3), "r"(b0), "r"(b1));
}
__device__ __forceinline__ void mma_f16(
    float& c0, float& c1, float& c2, float& c3,
    unsigned a0, unsigned a1, unsigned a2, unsigned a3,
    unsigned b0, unsigned b1) {
    asm("mma.sync.aligned.m16n8k16.row.col.f32.f16.f16.f32 "
        "{%0,%1,%2,%3}, {%4,%5,%6,%7}, {%8,%9}, {%0,%1,%2,%3};"
        : "+f"(c0), "+f"(c1), "+f"(c2), "+f"(c3)
        : "r"(a0), "r"(a1), "r"(a2), "r"(a3), "r"(b0), "r"(b1));
}
__device__ __forceinline__ unsigned packh2(float lo, float hi) {
    __half2 h = __floats2half2_rn(lo, hi);
    return *(unsigned*)&h;
}

// ============================================================================
// Kernel 1: projections via tf32 mma, split-x. N-tile = 128. fp16 outputs.
// ============================================================================
__global__ void __launch_bounds__(256) proj_tc_kernel(
    const float* __restrict__ x,
    const float* __restrict__ wt, const float* __restrict__ bt,
    const float* __restrict__ wp, const float* __restrict__ bp,
    const float* __restrict__ wg, const float* __restrict__ bg) {
    extern __shared__ float sm[];
    float* ws = sm;                 // [32][36]
    float* xh = sm + 32 * 36;       // [32][136]
    float* xl = xh + 32 * 136;      // [32][136]

    const int b  = blockIdx.y;
    const int Mbase = (blockIdx.x >> 5) * 32;
    const int N0    = (blockIdx.x & 31) * 128;
    const int tid  = threadIdx.x;
    const int wid  = tid >> 5, lane = tid & 31;
    const int m0   = (wid >> 2) * 16;
    const int n0w  = (wid & 3) * 32;
    const int qr = lane >> 2, qc = lane & 3;

    float acc[4][4];
#pragma unroll
    for (int nt = 0; nt < 4; nt++)
#pragma unroll
        for (int j = 0; j < 4; j++) acc[nt][j] = 0.f;

    for (int kp = 0; kp < 8; kp++) {
        const int k0 = kp * 32;
        __syncthreads();
#pragma unroll
        for (int i = 0; i < 4; i++) {
            int idx = i * 256 + tid;
            int r = idx >> 5, kk = idx & 31;
            int o = Mbase + r;
            const float* src = (o < 32) ? wt + o * C_
                             : (o < 64) ? wp + (o - 32) * C_
                                        : wg + (o - 64) * C_;
            ws[r * 36 + kk] = cvt_tf32f(src[k0 + kk]);
        }
#pragma unroll
        for (int i = 0; i < 4; i++) {
            int idx = i * 256 + tid;
            int cc = idx >> 5, nn4 = idx & 31;
            float4 v = *(const float4*)(
                x + ((size_t)(b * C_ + k0 + cc)) * N_ + N0 + nn4 * 4);
            float4 h, l;
            h.x = cvt_tf32f(v.x); l.x = v.x - h.x;
            h.y = cvt_tf32f(v.y); l.y = v.y - h.y;
            h.z = cvt_tf32f(v.z); l.z = v.z - h.z;
            h.w = cvt_tf32f(v.w); l.w = v.w - h.w;
            *(float4*)(xh + cc * 136 + nn4 * 4) = h;
            *(float4*)(xl + cc * 136 + nn4 * 4) = l;
        }
        __syncthreads();

#pragma unroll
        for (int ks = 0; ks < 4; ks++) {
            const float* wrow = ws + (m0 + qr) * 36 + ks * 8 + qc;
            unsigned a0 = __float_as_uint(wrow[0]);
            unsigned a1 = __float_as_uint(wrow[8 * 36]);
            unsigned a2 = __float_as_uint(wrow[4]);
            unsigned a3 = __float_as_uint(wrow[8 * 36 + 4]);
            const float* bh = xh + (ks * 8 + qc) * 136 + n0w + qr;
            const float* bl = xl + (ks * 8 + qc) * 136 + n0w + qr;
#pragma unroll
            for (int nt = 0; nt < 4; nt++) {
                unsigned b0 = __float_as_uint(bh[nt * 8]);
                unsigned b1 = __float_as_uint(bh[4 * 136 + nt * 8]);
                mma_tf32(acc[nt][0], acc[nt][1], acc[nt][2], acc[nt][3],
                         a0, a1, a2, a3, b0, b1);
                unsigned l0 = __float_as_uint(bl[nt * 8]);
                unsigned l1 = __float_as_uint(bl[4 * 136 + nt * 8]);
                mma_tf32(acc[nt][0], acc[nt][1], acc[nt][2], acc[nt][3],
                         a0, a1, a2, a3, l0, l1);
            }
        }
    }

    const float LOG2E = 1.4426950408889634f;
#pragma unroll
    for (int rr = 0; rr < 2; rr++) {
        int o = Mbase + m0 + qr + rr * 8;
        if (o < 32) {
            float bias = bt[o];
            __half2* dst = (__half2*)(d_theta + ((size_t)b * C8_ + o) * N_ +
                                      N0 + n0w + qc * 2);
#pragma unroll
            for (int nt = 0; nt < 4; nt++)
                dst[nt * 4] = __floats2half2_rn(
                    (acc[nt][rr * 2] + bias) * LOG2E,
                    (acc[nt][rr * 2 + 1] + bias) * LOG2E);
        } else if (o < 64) {
            float bias = bp[o - 32];
            __half2* dst = (__half2*)(d_phi + ((size_t)b * C8_ + (o - 32)) * N_ +
                                      N0 + n0w + qc * 2);
#pragma unroll
            for (int nt = 0; nt < 4; nt++)
                dst[nt * 4] = __floats2half2_rn(
                    acc[nt][rr * 2] + bias, acc[nt][rr * 2 + 1] + bias);
        } else {
            float bias = bg[o - 64];
            __half2* dst = (__half2*)(d_g + ((size_t)b * C2_ + (o - 64)) * N_ +
                                      N0 + n0w + qc * 2);
#pragma unroll
            for (int nt = 0; nt < 4; nt++)
                dst[nt * 4] = __floats2half2_rn(
                    acc[nt][rr * 2] + bias, acc[nt][rr * 2 + 1] + bias);
        }
    }
}

// ============================================================================
// Kernel 2: fp16 flash attention, online-max softmax, zero-shuffle P.
// CTA = 128 thr (4 warps x 16 q rows), key tile 64.
// phi_s [64 key][stride 40 half]; g_s [128 c2][stride 72 half] (key-major).
// ============================================================================
#define PHI_STR 40
#define G_STR   72

__global__ void __launch_bounds__(128, 2) flash_tc_kernel() {
    extern __shared__ __half smh[];
    __half* phi_s = smh;                     // 64*40 halves
    __half* g_s   = smh + 64 * PHI_STR;      // 128*72 halves

    const int b   = blockIdx.y;
    const int q0  = blockIdx.x * 64;
    const int tid = threadIdx.x;
    const int w    = tid >> 5;
    const int lane = tid & 31;
    const int qr = lane >> 2;
    const int qc = lane & 3;
    const int row0 = q0 + w * 16 + qr;

    // theta A-fragments (fp16, log2e already folded at proj)
    unsigned at[2][4];
    {
        const __half* tp = d_theta + (size_t)b * C8_ * N_;
#pragma unroll
        for (int ks = 0; ks < 2; ks++) {
            int c = ks * 16 + 2 * qc;
            at[ks][0] = packh2(__half2float(tp[(size_t)c * N_ + row0]),
                               __half2float(tp[(size_t)(c + 1) * N_ + row0]));
            at[ks][1] = packh2(__half2float(tp[(size_t)c * N_ + row0 + 8]),
                               __half2float(tp[(size_t)(c + 1) * N_ + row0 + 8]));
            at[ks][2] = packh2(__half2float(tp[(size_t)(c + 8) * N_ + row0]),
                               __half2float(tp[(size_t)(c + 9) * N_ + row0]));
            at[ks][3] = packh2(__half2float(tp[(size_t)(c + 8) * N_ + row0 + 8]),
                               __half2float(tp[(size_t)(c + 9) * N_ + row0 + 8]));
        }
    }

    float O[16][4];
#pragma unroll
    for (int nt = 0; nt < 16; nt++)
#pragma unroll
        for (int j = 0; j < 4; j++) O[nt][j] = 0.f;
    float m0 = -1e30f, m1 = -1e30f, l0 = 0.f, l1 = 0.f;

    for (int kt = 0; kt < N_; kt += 64) {
        __syncthreads();
        // stage phi [64 key][32 c] fp16 (transpose from [c][n])
#pragma unroll
        for (int i = 0; i < 8; i++) {
            int idx = i * 128 + tid;             // 0..1023
            int c = idx >> 5, kc = idx & 31;     // kc = key pair index
            __half2 v = *(const __half2*)(
                d_phi + ((size_t)b * C8_ + c) * N_ + kt + kc * 2);
            phi_s[(kc * 2) * PHI_STR + c]     = __low2half(v);
            phi_s[(kc * 2 + 1) * PHI_STR + c] = __high2half(v);
        }
        // stage g [128 c2][64 key] fp16 (key-contiguous, from [c2][n])
#pragma unroll
        for (int i = 0; i < 16; i++) {
            int idx = i * 128 + tid;             // 0..2047
            int c2 = idx >> 4, kq = idx & 15;    // 4 keys per chunk
            uint2 v = *(const uint2*)(
                d_g + ((size_t)b * C2_ + c2) * N_ + kt + kq * 4);
            *(uint2*)(g_s + c2 * G_STR + kq * 4) = v;
        }
        __syncthreads();

        // ---- GEMM1: S[16q x 64k] = theta @ phi^T (fp16, K=32 -> 2 mma/nt)
        float s[8][4];
#pragma unroll
        for (int nt = 0; nt < 8; nt++)
#pragma unroll
            for (int j = 0; j < 4; j++) s[nt][j] = 0.f;

#pragma unroll
        for (int ks = 0; ks < 2; ks++) {
#pragma unroll
            for (int nt = 0; nt < 8; nt++) {
                const __half* pb = phi_s + (nt * 8 + qr) * PHI_STR + ks * 16 + 2 * qc;
                unsigned b0 = *(const unsigned*)pb;
                unsigned b1 = *(const unsigned*)(pb + 8);
                mma_f16(s[nt][0], s[nt][1], s[nt][2], s[nt][3],
                        at[ks][0], at[ks][1], at[ks][2], at[ks][3], b0, b1);
            }
        }

        // ---- online-max softmax (scores already in log2 domain) ----
        float rm0 = -1e30f, rm1 = -1e30f;
#pragma unroll
        for (int nt = 0; nt < 8; nt++) {
            rm0 = fmaxf(rm0, fmaxf(s[nt][0], s[nt][1]));
            rm1 = fmaxf(rm1, fmaxf(s[nt][2], s[nt][3]));
        }
        rm0 = fmaxf(rm0, __shfl_xor_sync(0xffffffffu, rm0, 1, 4));
        rm0 = fmaxf(rm0, __shfl_xor_sync(0xffffffffu, rm0, 2, 4));
        rm1 = fmaxf(rm1, __shfl_xor_sync(0xffffffffu, rm1, 1, 4));
        rm1 = fmaxf(rm1, __shfl_xor_sync(0xffffffffu, rm1, 2, 4));
        float mn0 = fmaxf(m0, rm0), mn1 = fmaxf(m1, rm1);
        float cr0 = ex2f(m0 - mn0), cr1 = ex2f(m1 - mn1);
        m0 = mn0; m1 = mn1;
#pragma unroll
        for (int nt = 0; nt < 16; nt++) {
            O[nt][0] *= cr0; O[nt][1] *= cr0;
            O[nt][2] *= cr1; O[nt][3] *= cr1;
        }

        unsigned pk[8][2];
        float rs0 = 0.f, rs1 = 0.f;
#pragma unroll
        for (int nt = 0; nt < 8; nt++) {
            float e0 = ex2f(s[nt][0] - mn0);
            float e1 = ex2f(s[nt][1] - mn0);
            float e2 = ex2f(s[nt][2] - mn1);
            float e3 = ex2f(s[nt][3] - mn1);
            rs0 += e0 + e1; rs1 += e2 + e3;
            pk[nt][0] = packh2(e0, e1);
            pk[nt][1] = packh2(e2, e3);
        }
        l0 = l0 * cr0 + rs0;
        l1 = l1 * cr1 + rs1;

        // ---- GEMM2: O[16q x 128c2] += P @ g (fp16, K=64 -> 4 kb slices)
#pragma unroll
        for (int kb = 0; kb < 4; kb++) {
            unsigned a0 = pk[2 * kb][0];
            unsigned a1 = pk[2 * kb][1];
            unsigned a2 = pk[2 * kb + 1][0];
            unsigned a3 = pk[2 * kb + 1][1];
#pragma unroll
            for (int nt = 0; nt < 16; nt++) {
                const __half* gb = g_s + (nt * 8 + qr) * G_STR + kb * 16 + 2 * qc;
                unsigned b0 = *(const unsigned*)gb;
                unsigned b1 = *(const unsigned*)(gb + 8);
                mma_f16(O[nt][0], O[nt][1], O[nt][2], O[nt][3],
                        a0, a1, a2, a3, b0, b1);
            }
        }
    }

    // finalize: reduce l within quads, normalize, store
    l0 += __shfl_xor_sync(0xffffffffu, l0, 1, 4);
    l0 += __shfl_xor_sync(0xffffffffu, l0, 2, 4);
    l1 += __shfl_xor_sync(0xffffffffu, l1, 1, 4);
    l1 += __shfl_xor_sync(0xffffffffu, l1, 2, 4);
    float inv0 = 1.0f / l0;
    float inv1 = 1.0f / l1;

    float* dst0 = d_att + ((size_t)b * N_ + row0) * C2_ + qc * 2;
#pragma unroll
    for (int nt = 0; nt < 16; nt++) {
        *(float2*)(dst0 + nt * 8) =
            make_float2(O[nt][0] * inv0, O[nt][1] * inv0);
        *(float2*)(dst0 + 8 * C2_ + nt * 8) =
            make_float2(O[nt][2] * inv1, O[nt][3] * inv1);
    }
}

// ============================================================================
// Kernel 3: out = w_o @ att + b_o + x via tf32 mma, split-att.
// ============================================================================
__global__ void __launch_bounds__(256) out_tc_kernel(
    const float* __restrict__ wo, const float* __restrict__ bo,
    const float* __restrict__ x, float* __restrict__ out) {
    extern __shared__ float sm[];
    float* w_s = sm;                // [32][132]
    float* ah  = sm + 32 * 132;     // [128][36]
    float* al  = ah + 128 * 36;     // [128][36]

    const int b  = blockIdx.y;
    const int Cbase = (blockIdx.x >> 5) * 32;
    const int N0    = (blockIdx.x & 31) * 128;
    const int tid  = threadIdx.x;
    const int wid  = tid >> 5, lane = tid & 31;
    const int m0   = (wid >> 2) * 16;
    const int n0w  = (wid & 3) * 32;
    const int qr = lane >> 2, qc = lane & 3;

#pragma unroll
    for (int i = 0; i < 16; i++) {
        int idx = i * 256 + tid;
        int r = idx >> 7, kk = idx & 127;
        w_s[r * 132 + kk] = cvt_tf32f(wo[(Cbase + r) * C2_ + kk]);
    }

    float acc[4][4];
#pragma unroll
    for (int nt = 0; nt < 4; nt++)
#pragma unroll
        for (int j = 0; j < 4; j++) acc[nt][j] = 0.f;

    for (int kp = 0; kp < 4; kp++) {
        const int k0 = kp * 32;
        __syncthreads();
#pragma unroll
        for (int i = 0; i < 4; i++) {
            int idx = i * 256 + tid;
            int nn = idx >> 3, kk4 = idx & 7;
            float4 v = *(const float4*)(
                d_att + ((size_t)b * N_ + N0 + nn) * C2_ + k0 + kk4 * 4);
            float4 h, l;
            h.x = cvt_tf32f(v.x); l.x = v.x - h.x;
            h.y = cvt_tf32f(v.y); l.y = v.y - h.y;
            h.z = cvt_tf32f(v.z); l.z = v.z - h.z;
            h.w = cvt_tf32f(v.w); l.w = v.w - h.w;
            *(float4*)(ah + nn * 36 + kk4 * 4) = h;
            *(float4*)(al + nn * 36 + kk4 * 4) = l;
        }
        __syncthreads();

#pragma unroll
        for (int ks = 0; ks < 4; ks++) {
            const float* wrow = w_s + (m0 + qr) * 132 + k0 + ks * 8 + qc;
            unsigned a0 = __float_as_uint(wrow[0]);
            unsigned a1 = __float_as_uint(wrow[8 * 132]);
            unsigned a2 = __float_as_uint(wrow[4]);
            unsigned a3 = __float_as_uint(wrow[8 * 132 + 4]);
#pragma unroll
            for (int nt = 0; nt < 4; nt++) {
                const float* bh = ah + (n0w + nt * 8 + qr) * 36 + ks * 8 + qc;
                const float* bl = al + (n0w + nt * 8 + qr) * 36 + ks * 8 + qc;
                unsigned b0 = __float_as_uint(bh[0]);
                unsigned b1 = __float_as_uint(bh[4]);
                mma_tf32(acc[nt][0], acc[nt][1], acc[nt][2], acc[nt][3],
                         a0, a1, a2, a3, b0, b1);
                unsigned c0 = __float_as_uint(bl[0]);
                unsigned c1 = __float_as_uint(bl[4]);
                mma_tf32(acc[nt][0], acc[nt][1], acc[nt][2], acc[nt][3],
                         a0, a1, a2, a3, c0, c1);
            }
        }
    }

#pragma unroll
    for (int rr = 0; rr < 2; rr++) {
        int c = Cbase + m0 + qr + rr * 8;
        float bias = bo[c];
#pragma unroll
        for (int nt = 0; nt < 4; nt++) {
            int n = N0 + n0w + qc * 2 + nt * 8;
            size_t idx = ((size_t)b * C_ + c) * N_ + n;
            float2 xv = *(const float2*)(x + idx);
            *(float2*)(out + idx) = make_float2(
                acc[nt][rr * 2] + bias + xv.x,
                acc[nt][rr * 2 + 1] + bias + xv.y);
        }
    }
}

// ============================================================================
extern "C" void kernel_launch(void* const* d_in, const int* in_sizes, int n_in,
                              void* d_out, int out_size) {
    (void)in_sizes; (void)n_in; (void)out_size;
    const float* x  = (const float*)d_in[0];
    const float* wt = (const float*)d_in[1];
    const float* bt = (const float*)d_in[2];
    const float* wp = (const float*)d_in[3];
    const float* bp = (const float*)d_in[4];
    const float* wg = (const float*)d_in[5];
    const float* bg = (const float*)d_in[6];
    const float* wo = (const float*)d_in[7];
    const float* bo = (const float*)d_in[8];
    float* out = (float*)d_out;

    const int smem_proj  = (32 * 36 + 2 * 32 * 136) * 4;         // 39424
    const int smem_flash = (64 * PHI_STR + 128 * G_STR) * 2;     // 23552
    const int smem_out   = (32 * 132 + 2 * 128 * 36) * 4;        // 53760

    cudaFuncSetAttribute(proj_tc_kernel,
                         cudaFuncAttributeMaxDynamicSharedMemorySize, smem_proj);
    cudaFuncSetAttribute(flash_tc_kernel,
                         cudaFuncAttributeMaxDynamicSharedMemorySize, smem_flash);
    cudaFuncSetAttribute(out_tc_kernel,
                         cudaFuncAttributeMaxDynamicSharedMemorySize, smem_out);

    proj_tc_kernel<<<dim3(192, B_), 256, smem_proj>>>(x, wt, bt, wp, bp, wg, bg);
    flash_tc_kernel<<<dim3(N_ / 64, B_), 128, smem_flash>>>();
    out_tc_kernel<<<dim3(256, B_), 256, smem_out>>>(wo, bo, x, out);
}